// round 1
// baseline (speedup 1.0000x reference)
#include <cuda_runtime.h>

#define PN 4
#define LN 512
#define DN 64

// ---------------- device scratch (no allocations allowed) ----------------
__device__ float    g_s[PN * LN * LN];     // 4 MB distance/score matrix
__device__ float    g_rm[PN * LN];         // row max
__device__ float    g_rs[PN * LN];         // row sum-exp
__device__ unsigned g_cmk[PN * LN];        // col max (monotonic uint key)
__device__ float    g_csp[PN * LN * 8];    // col sum-exp partials (8 j-chunks)
__device__ float    g_cs[PN * LN];         // col sum-exp
__device__ float    g_pnum[PN * 64];       // per-block partial num
__device__ float    g_pden[PN * 64];       // per-block partial den

// Order-preserving float<->uint key (works for all finite floats).
__device__ __forceinline__ unsigned fkey(float f) {
    unsigned u = __float_as_uint(f);
    return (u & 0x80000000u) ? ~u : (u | 0x80000000u);
}
__device__ __forceinline__ float funkey(unsigned k) {
    return (k & 0x80000000u) ? __uint_as_float(k ^ 0x80000000u)
                             : __uint_as_float(~k);
}

// ---------------- init: reset col-max keys ----------------
__global__ void k_init() {
    int t = blockIdx.x * 256 + threadIdx.x;
    if (t < PN * LN) g_cmk[t] = 0u;   // key 0 == NaN sentinel, loses every max
}

// ---------------- K1: 32x32 tiles of s = -sum_d |z0 - z1| ----------------
// Transposed smem layout [d][row], pitch 36 floats: d*144B is 16B-aligned for
// LDS.128; compute-phase reads are bank-conflict-free.
__global__ __launch_bounds__(128) void k_s(const float* __restrict__ z) {
    __shared__ __align__(16) float z0s[DN][36];
    __shared__ __align__(16) float z1s[DN][36];
    const int p  = blockIdx.z;
    const int j0 = blockIdx.y * 32;
    const int k0 = blockIdx.x * 32;
    const int t  = threadIdx.x;
    const float* z0 = z + (size_t)p        * LN * DN;
    const float* z1 = z + (size_t)(p + PN) * LN * DN;

    // load 32x64 tiles (coalesced global, consecutive lanes -> consecutive d)
    #pragma unroll
    for (int i = 0; i < 16; i++) {
        int idx = t + i * 128;
        int r = idx >> 6, d = idx & 63;
        z0s[d][r] = z0[(j0 + r) * DN + d];
        z1s[d][r] = z1[(k0 + r) * DN + d];
    }
    __syncthreads();

    const int tx = t & 15, ty = t >> 4;   // 16 x 8 threads, 2 x 4 microtile
    float acc[4][2];
    #pragma unroll
    for (int i = 0; i < 4; i++) { acc[i][0] = 0.f; acc[i][1] = 0.f; }

    #pragma unroll
    for (int d = 0; d < DN; d++) {
        float4 a = *(const float4*)&z0s[d][ty * 4];
        float2 b = *(const float2*)&z1s[d][tx * 2];
        acc[0][0] += fabsf(a.x - b.x);
        acc[0][1] += fabsf(a.x - b.y);
        acc[1][0] += fabsf(a.y - b.x);
        acc[1][1] += fabsf(a.y - b.y);
        acc[2][0] += fabsf(a.z - b.x);
        acc[2][1] += fabsf(a.z - b.y);
        acc[3][0] += fabsf(a.w - b.x);
        acc[3][1] += fabsf(a.w - b.y);
    }

    #pragma unroll
    for (int i = 0; i < 4; i++) {
        float2 v = make_float2(-acc[i][0], -acc[i][1]);
        *(float2*)&g_s[((size_t)p * LN + j0 + ty * 4 + i) * LN + k0 + tx * 2] = v;
    }
}

// ---------------- K2: row max + row sum-exp (one block per row) ----------------
__global__ __launch_bounds__(128) void k_row() {
    const int j = blockIdx.x, p = blockIdx.y;
    const int t = threadIdx.x;
    const float* row = g_s + ((size_t)p * LN + j) * LN;
    float x0 = row[t], x1 = row[t + 128], x2 = row[t + 256], x3 = row[t + 384];
    float m = fmaxf(fmaxf(x0, x1), fmaxf(x2, x3));
    #pragma unroll
    for (int o = 16; o; o >>= 1) m = fmaxf(m, __shfl_xor_sync(0xffffffffu, m, o));
    __shared__ float sm[4], ss[4];
    if ((t & 31) == 0) sm[t >> 5] = m;
    __syncthreads();
    m = fmaxf(fmaxf(sm[0], sm[1]), fmaxf(sm[2], sm[3]));
    float s = __expf(x0 - m) + __expf(x1 - m) + __expf(x2 - m) + __expf(x3 - m);
    #pragma unroll
    for (int o = 16; o; o >>= 1) s += __shfl_xor_sync(0xffffffffu, s, o);
    if ((t & 31) == 0) ss[t >> 5] = s;
    __syncthreads();
    if (t == 0) {
        g_rm[p * LN + j] = m;
        g_rs[p * LN + j] = ss[0] + ss[1] + ss[2] + ss[3];
    }
}

// ---------------- K3: col max (atomicMax on monotonic key, deterministic) ----
__global__ __launch_bounds__(128) void k_cmax() {
    const int jc = blockIdx.x, kg = blockIdx.y, p = blockIdx.z;
    const int k = kg * 128 + threadIdx.x;
    const float* base = g_s + (size_t)p * LN * LN + (size_t)jc * 64 * LN + k;
    float m = -3.402823466e38f;
    #pragma unroll 8
    for (int j = 0; j < 64; j++) m = fmaxf(m, base[(size_t)j * LN]);
    atomicMax(&g_cmk[p * LN + k], fkey(m));
}

// ---------------- K4: col sum-exp partials (deterministic, no float atomics) --
__global__ __launch_bounds__(128) void k_csum() {
    const int jc = blockIdx.x, kg = blockIdx.y, p = blockIdx.z;
    const int k = kg * 128 + threadIdx.x;
    const float* base = g_s + (size_t)p * LN * LN + (size_t)jc * 64 * LN + k;
    float m = funkey(g_cmk[p * LN + k]);
    float s = 0.f;
    #pragma unroll 8
    for (int j = 0; j < 64; j++) s += __expf(base[(size_t)j * LN] - m);
    g_csp[(p * LN + k) * 8 + jc] = s;
}

__global__ __launch_bounds__(128) void k_cfin() {
    const int kg = blockIdx.x, p = blockIdx.y;
    const int k = kg * 128 + threadIdx.x;
    float s = 0.f;
    #pragma unroll
    for (int jc = 0; jc < 8; jc++) s += g_csp[(p * LN + k) * 8 + jc];
    g_cs[p * LN + k] = s;
}

// ---------------- K5: sum(c*s), sum(c) partials ----------------
__global__ __launch_bounds__(256) void k_red() {
    const int p = blockIdx.x, chunk = blockIdx.y;
    const int t = threadIdx.x;
    const float*    S   = g_s   + (size_t)p * LN * LN;
    const float*    rm  = g_rm  + p * LN;
    const float*    rs  = g_rs  + p * LN;
    const unsigned* cmk = g_cmk + p * LN;
    const float*    cs  = g_cs  + p * LN;
    float num = 0.f, den = 0.f;
    #pragma unroll
    for (int i = 0; i < 16; i++) {
        int e = chunk * 4096 + i * 256 + t;
        int j = e >> 9, k = e & 511;
        float sv = S[e];
        float a = __expf(sv - rm[j]) * (1.0f / rs[j]);
        float b = __expf(sv - funkey(cmk[k])) * (1.0f / cs[k]);
        float c = a + b - a * b;
        num = fmaf(c, sv, num);
        den += c;
    }
    #pragma unroll
    for (int o = 16; o; o >>= 1) {
        num += __shfl_xor_sync(0xffffffffu, num, o);
        den += __shfl_xor_sync(0xffffffffu, den, o);
    }
    __shared__ float sn[8], sd[8];
    if ((t & 31) == 0) { sn[t >> 5] = num; sd[t >> 5] = den; }
    __syncthreads();
    if (t == 0) {
        float N = 0.f, Dd = 0.f;
        #pragma unroll
        for (int w = 0; w < 8; w++) { N += sn[w]; Dd += sd[w]; }
        g_pnum[p * 64 + chunk] = N;
        g_pden[p * 64 + chunk] = Dd;
    }
}

// ---------------- K6: final 16 outputs ----------------
__global__ void k_final(const float* __restrict__ w, const float* __restrict__ b,
                        float* __restrict__ out) {
    const int t = threadIdx.x;
    if (t >= 16) return;
    const int p = t >> 2, c = t & 3;
    float n = 0.f, d = 0.f;
    for (int i = 0; i < 64; i++) { n += g_pnum[p * 64 + i]; d += g_pden[p * 64 + i]; }
    out[t] = (n / d) * w[c] + b[c];
}

// ---------------- launch ----------------
extern "C" void kernel_launch(void* const* d_in, const int* in_sizes, int n_in,
                              void* d_out, int out_size) {
    const float* z = (const float*)d_in[0];   // (8, 512, 64) fp32
    const float* w = (const float*)d_in[1];   // (1, 4)
    const float* b = (const float*)d_in[2];   // (4,)
    float* out = (float*)d_out;               // (4, 4)

    k_init <<<8, 256>>>();
    k_s    <<<dim3(16, 16, 4), 128>>>(z);
    k_row  <<<dim3(512, 4),    128>>>();
    k_cmax <<<dim3(8, 4, 4),   128>>>();
    k_csum <<<dim3(8, 4, 4),   128>>>();
    k_cfin <<<dim3(4, 4),      128>>>();
    k_red  <<<dim3(4, 64),     256>>>();
    k_final<<<1, 16>>>(w, b, out);
}

// round 2
// speedup vs baseline: 1.4556x; 1.4556x over previous
#include <cuda_runtime.h>

#define PN 4
#define LN 512
#define DN 64

typedef unsigned long long ull;

// ---------------- device scratch ----------------
__device__ float g_s[PN * LN * LN];       // 4 MB score matrix
__device__ float g_rpm[PN * LN * 16];     // row partial max   (16 k-blocks)
__device__ float g_rps[PN * LN * 16];     // row partial sumexp
__device__ float g_cpm[PN * LN * 8];      // col partial max   (8 j-blocks)
__device__ float g_cps[PN * LN * 8];      // col partial sumexp
__device__ float g_rm [PN * LN];          // row max
__device__ float g_rsi[PN * LN];          // 1 / row sumexp
__device__ float g_cm [PN * LN];          // col max
__device__ float g_csi[PN * LN];          // 1 / col sumexp
__device__ float g_pnum[PN * 64];
__device__ float g_pden[PN * 64];

// ---- packed f32x2 helpers ----
__device__ __forceinline__ ull add2(ull a, ull b) {
    ull r; asm("add.rn.f32x2 %0, %1, %2;" : "=l"(r) : "l"(a), "l"(b)); return r;
}
__device__ __forceinline__ ull pack2(float lo, float hi) {
    ull r; asm("mov.b64 %0, {%1,%2};" : "=l"(r) : "f"(lo), "f"(hi)); return r;
}
__device__ __forceinline__ void unpack2(ull v, float& lo, float& hi) {
    asm("mov.b64 {%0,%1}, %2;" : "=f"(lo), "=f"(hi) : "l"(v));
}

// ============ K1: 64(j) x 32(k) tiles of s = -sum_d |z0-z1| + partial stats ====
// z0 stored duplicated [d][2j,2j+1]; z1 stored negated.  Per element pair:
// 1x add.f32x2 (diff) + 2x LOP3 (abs) + 1x add.f32x2 (acc) -> fma & alu pipes balanced.
__global__ __launch_bounds__(128) void k_s(const float* __restrict__ z) {
    __shared__ __align__(16) float z0d[DN][140];   // duplicated, 35 KB
    __shared__ __align__(16) float z1n[DN][36];    // negated,     9 KB
    __shared__ float scm[4][32], scs[4][32], scmf[32];

    const int kb = blockIdx.x;           // 0..15
    const int jb = blockIdx.y;           // 0..7
    const int p  = blockIdx.z;
    const int j0 = jb * 64, k0 = kb * 32;
    const int t  = threadIdx.x;
    const int tx = t & 7;                // k quad: cols tx*4..+3
    const int ty = t >> 3;               // j quad: rows ty*4..+3
    const int w  = t >> 5;

    const float* z0 = z + (size_t)p        * LN * DN;
    const float* z1 = z + (size_t)(p + PN) * LN * DN;

    #pragma unroll
    for (int i = 0; i < 32; i++) {
        int idx = t + i * 128;
        int r = idx >> 6, d = idx & 63;
        float v = z0[(j0 + r) * DN + d];
        z0d[d][2 * r] = v; z0d[d][2 * r + 1] = v;
    }
    #pragma unroll
    for (int i = 0; i < 16; i++) {
        int idx = t + i * 128;
        int r = idx >> 6, d = idx & 63;
        z1n[d][r] = -z1[(k0 + r) * DN + d];
    }
    __syncthreads();

    ull acc[4][2];
    #pragma unroll
    for (int j = 0; j < 4; j++) { acc[j][0] = 0; acc[j][1] = 0; }

    #pragma unroll 8
    for (int d = 0; d < DN; d++) {
        float4 aA = *(const float4*)&z0d[d][ty * 8];       // (aj0,aj0,aj1,aj1)
        float4 aB = *(const float4*)&z0d[d][ty * 8 + 4];   // (aj2,aj2,aj3,aj3)
        float4 bb = *(const float4*)&z1n[d][tx * 4];       // -b[k..k+3]
        ull ap[4] = { pack2(aA.x, aA.y), pack2(aA.z, aA.w),
                      pack2(aB.x, aB.y), pack2(aB.z, aB.w) };
        ull bp[2] = { pack2(bb.x, bb.y), pack2(bb.z, bb.w) };
        #pragma unroll
        for (int j = 0; j < 4; j++)
            #pragma unroll
            for (int kp = 0; kp < 2; kp++) {
                ull df = add2(ap[j], bp[kp]);              // a - b
                df &= 0x7fffffff7fffffffULL;               // |.| (2x LOP3, alu pipe)
                acc[j][kp] = add2(acc[j][kp], df);
            }
    }

    // unpack, negate, store
    float s[4][4];
    #pragma unroll
    for (int j = 0; j < 4; j++) {
        float l0, h0, l1, h1;
        unpack2(acc[j][0], l0, h0); unpack2(acc[j][1], l1, h1);
        s[j][0] = -l0; s[j][1] = -h0; s[j][2] = -l1; s[j][3] = -h1;
        *(float4*)&g_s[((size_t)p * LN + j0 + ty * 4 + j) * LN + k0 + tx * 4] =
            make_float4(s[j][0], s[j][1], s[j][2], s[j][3]);
    }

    // ---- row partials over this block's 32 cols (shfl across tx octet) ----
    #pragma unroll
    for (int j = 0; j < 4; j++) {
        float m = fmaxf(fmaxf(s[j][0], s[j][1]), fmaxf(s[j][2], s[j][3]));
        #pragma unroll
        for (int o = 1; o <= 4; o <<= 1) m = fmaxf(m, __shfl_xor_sync(~0u, m, o));
        float e = __expf(s[j][0] - m) + __expf(s[j][1] - m) +
                  __expf(s[j][2] - m) + __expf(s[j][3] - m);
        #pragma unroll
        for (int o = 1; o <= 4; o <<= 1) e += __shfl_xor_sync(~0u, e, o);
        if (tx == 0) {
            int jg = j0 + ty * 4 + j;
            g_rpm[((size_t)p * LN + jg) * 16 + kb] = m;
            g_rps[((size_t)p * LN + jg) * 16 + kb] = e;
        }
    }

    // ---- col partials over this block's 64 rows ----
    float cmx[4];
    #pragma unroll
    for (int k = 0; k < 4; k++) {
        float m = fmaxf(fmaxf(s[0][k], s[1][k]), fmaxf(s[2][k], s[3][k]));
        m = fmaxf(m, __shfl_xor_sync(~0u, m, 8));
        m = fmaxf(m, __shfl_xor_sync(~0u, m, 16));
        cmx[k] = m;                                     // max over 16 rows (this warp)
    }
    if ((t & 24) == 0)
        #pragma unroll
        for (int k = 0; k < 4; k++) scm[w][tx * 4 + k] = cmx[k];
    __syncthreads();
    if (t < 32)
        scmf[t] = fmaxf(fmaxf(scm[0][t], scm[1][t]), fmaxf(scm[2][t], scm[3][t]));
    __syncthreads();
    #pragma unroll
    for (int k = 0; k < 4; k++) {
        float M = scmf[tx * 4 + k];
        float e = __expf(s[0][k] - M) + __expf(s[1][k] - M) +
                  __expf(s[2][k] - M) + __expf(s[3][k] - M);
        e += __shfl_xor_sync(~0u, e, 8);
        e += __shfl_xor_sync(~0u, e, 16);
        cmx[k] = e;
    }
    if ((t & 24) == 0)
        #pragma unroll
        for (int k = 0; k < 4; k++) scs[w][tx * 4 + k] = cmx[k];
    __syncthreads();
    if (t < 32) {
        int kg = k0 + t;
        g_cpm[((size_t)p * LN + kg) * 8 + jb] = scmf[t];
        g_cps[((size_t)p * LN + kg) * 8 + jb] = scs[0][t] + scs[1][t] + scs[2][t] + scs[3][t];
    }
}

// ============ K2: ordered combine of partials (deterministic) ============
__global__ __launch_bounds__(256) void k_comb() {
    int gt = blockIdx.x * 256 + threadIdx.x;
    if (gt < PN * LN) {                           // rows
        int base = gt * 16;
        float M = g_rpm[base];
        #pragma unroll
        for (int i = 1; i < 16; i++) M = fmaxf(M, g_rpm[base + i]);
        float S = 0.f;
        #pragma unroll
        for (int i = 0; i < 16; i++) S += g_rps[base + i] * __expf(g_rpm[base + i] - M);
        g_rm[gt] = M; g_rsi[gt] = 1.0f / S;
    } else {                                      // cols
        int c = gt - PN * LN;
        int base = c * 8;
        float M = g_cpm[base];
        #pragma unroll
        for (int i = 1; i < 8; i++) M = fmaxf(M, g_cpm[base + i]);
        float S = 0.f;
        #pragma unroll
        for (int i = 0; i < 8; i++) S += g_cps[base + i] * __expf(g_cpm[base + i] - M);
        g_cm[c] = M; g_csi[c] = 1.0f / S;
    }
}

// ============ K3: sum(c*s), sum(c) partials ============
__global__ __launch_bounds__(256) void k_red() {
    const int p = blockIdx.x, chunk = blockIdx.y;   // 64 chunks of 4096 elems
    const int t = threadIdx.x;
    const float* S   = g_s   + (size_t)p * LN * LN;
    const float* rm  = g_rm  + p * LN;
    const float* rsi = g_rsi + p * LN;
    const float* cm  = g_cm  + p * LN;
    const float* csi = g_csi + p * LN;
    float num = 0.f, den = 0.f;
    #pragma unroll
    for (int i = 0; i < 4; i++) {
        int e = chunk * 4096 + i * 1024 + t * 4;
        int j = e >> 9, k = e & 511;
        float4 sv = *(const float4*)&S[e];
        float4 cmv = *(const float4*)&cm[k];
        float4 civ = *(const float4*)&csi[k];
        float rmj = rm[j], rij = rsi[j];
        float a, b, c;
        a = __expf(sv.x - rmj) * rij; b = __expf(sv.x - cmv.x) * civ.x;
        c = a + b - a * b; num = fmaf(c, sv.x, num); den += c;
        a = __expf(sv.y - rmj) * rij; b = __expf(sv.y - cmv.y) * civ.y;
        c = a + b - a * b; num = fmaf(c, sv.y, num); den += c;
        a = __expf(sv.z - rmj) * rij; b = __expf(sv.z - cmv.z) * civ.z;
        c = a + b - a * b; num = fmaf(c, sv.z, num); den += c;
        a = __expf(sv.w - rmj) * rij; b = __expf(sv.w - cmv.w) * civ.w;
        c = a + b - a * b; num = fmaf(c, sv.w, num); den += c;
    }
    #pragma unroll
    for (int o = 16; o; o >>= 1) {
        num += __shfl_xor_sync(~0u, num, o);
        den += __shfl_xor_sync(~0u, den, o);
    }
    __shared__ float sn[8], sd[8];
    if ((t & 31) == 0) { sn[t >> 5] = num; sd[t >> 5] = den; }
    __syncthreads();
    if (t == 0) {
        float N = 0.f, D = 0.f;
        #pragma unroll
        for (int wq = 0; wq < 8; wq++) { N += sn[wq]; D += sd[wq]; }
        g_pnum[p * 64 + chunk] = N;
        g_pden[p * 64 + chunk] = D;
    }
}

// ============ K4: final 16 outputs ============
__global__ void k_final(const float* __restrict__ w, const float* __restrict__ b,
                        float* __restrict__ out) {
    const int t = threadIdx.x;
    if (t >= 16) return;
    const int p = t >> 2, c = t & 3;
    float n = 0.f, d = 0.f;
    for (int i = 0; i < 64; i++) { n += g_pnum[p * 64 + i]; d += g_pden[p * 64 + i]; }
    out[t] = (n / d) * w[c] + b[c];
}

// ---------------- launch ----------------
extern "C" void kernel_launch(void* const* d_in, const int* in_sizes, int n_in,
                              void* d_out, int out_size) {
    const float* z = (const float*)d_in[0];   // (8, 512, 64) fp32
    const float* w = (const float*)d_in[1];   // (1, 4)
    const float* b = (const float*)d_in[2];   // (4,)
    float* out = (float*)d_out;               // (4, 4)

    k_s    <<<dim3(16, 8, 4), 128>>>(z);
    k_comb <<<16, 256>>>();
    k_red  <<<dim3(4, 64), 256>>>();
    k_final<<<1, 16>>>(w, b, out);
}

// round 3
// speedup vs baseline: 1.4576x; 1.0014x over previous
#include <cuda_runtime.h>

#define PN 4
#define LN 512
#define DN 64
typedef unsigned long long ull;

// ---------------- device scratch ----------------
__device__ __align__(16) float g_s[PN * LN * LN];   // 4 MB score matrix
__device__ __align__(16) float g_rpm[PN * LN * 8];  // row partial max (8 kb)
__device__ __align__(16) float g_rps[PN * LN * 8];  // row partial sumexp
__device__ __align__(16) float g_cpm[PN * LN * 8];  // col partial max (8 jb)
__device__ __align__(16) float g_cps[PN * LN * 8];  // col partial sumexp
__device__ __align__(16) float g_A[PN * LN];        // exp(-rowmax)/rowsum
__device__ __align__(16) float g_B[PN * LN];        // exp(-colmax)/colsum
__device__ float g_pn[64], g_pd[64];
__device__ unsigned g_bar[2];

__device__ __forceinline__ ull add2(ull a, ull b) {
    ull r; asm("add.rn.f32x2 %0, %1, %2;" : "=l"(r) : "l"(a), "l"(b)); return r;
}

// ============ K1: 64x64 tiles of s = -sum_d |z0-z1|, + partial softmax stats ==
// z0 in smem packed j-major (natural f32x2 pairs over j); z1 stored negated and
// DUPLICATED in bank-swizzled pair layout so b-loads are conflict-free LDS.64.
// Per element: 0.5 FADD2(diff) + 1 LOP3(abs) + 0.5 FADD2(acc).
__global__ __launch_bounds__(128) void k_s(const float* __restrict__ z) {
    extern __shared__ float smd[];
    float* z0s = smd;                 // [64][68]
    float* z1d = smd + 64 * 68;       // [64][130], pair p'=(k&3)*16+(k>>2)
    __shared__ float scm[4][64], scs[4][64], scmf[64];

    const int kb = blockIdx.x, jb = blockIdx.y, p = blockIdx.z;
    const int t = threadIdx.x;
    if (kb == 0 && jb == 0 && p == 0 && t == 0) { g_bar[0] = 0; g_bar[1] = 0; }
    const int j0 = jb * 64, k0 = kb * 64;
    const int tx = t & 15, ty = t >> 4, w = t >> 5;

    const float4* z0g = (const float4*)(z + ((size_t)p * LN + j0) * DN);
    const float4* z1g = (const float4*)(z + ((size_t)(p + PN) * LN + k0) * DN);

    #pragma unroll
    for (int i = 0; i < 8; i++) {
        int f = i * 128 + t;           // 0..1023 float4s
        int r = f >> 4, dq = f & 15;   // row, d-quad
        float4 v = z0g[f];
        z0s[(4 * dq + 0) * 68 + r] = v.x;
        z0s[(4 * dq + 1) * 68 + r] = v.y;
        z0s[(4 * dq + 2) * 68 + r] = v.z;
        z0s[(4 * dq + 3) * 68 + r] = v.w;
        float4 u = z1g[f];
        int pr = 2 * ((r & 3) * 16 + (r >> 2));
        *(float2*)(z1d + (4 * dq + 0) * 130 + pr) = make_float2(-u.x, -u.x);
        *(float2*)(z1d + (4 * dq + 1) * 130 + pr) = make_float2(-u.y, -u.y);
        *(float2*)(z1d + (4 * dq + 2) * 130 + pr) = make_float2(-u.z, -u.z);
        *(float2*)(z1d + (4 * dq + 3) * 130 + pr) = make_float2(-u.w, -u.w);
    }
    __syncthreads();

    // thread tile: j = j0 + ty*8 .. +7 (packed pairs), k = k0 + 4*tx .. +3
    ull acc[16];                       // [jp][i]
    #pragma unroll
    for (int q = 0; q < 16; q++) acc[q] = 0;

    #pragma unroll 4
    for (int d = 0; d < DN; d++) {
        ulonglong2 A01 = *(const ulonglong2*)(z0s + d * 68 + ty * 8);
        ulonglong2 A23 = *(const ulonglong2*)(z0s + d * 68 + ty * 8 + 4);
        ull av[4] = { A01.x, A01.y, A23.x, A23.y };
        #pragma unroll
        for (int i = 0; i < 4; i++) {
            ull bv = *(const ull*)(z1d + d * 130 + 32 * i + 2 * tx);  // (-bk,-bk)
            #pragma unroll
            for (int jp = 0; jp < 4; jp++) {
                ull df = add2(av[jp], bv);          // a - b (both halves)
                df &= 0x7fffffff7fffffffULL;        // |.|
                acc[jp * 4 + i] = add2(acc[jp * 4 + i], df);
            }
        }
    }

    // unpack to s[jj][i], negate, store
    float s[8][4];
    #pragma unroll
    for (int jp = 0; jp < 4; jp++)
        #pragma unroll
        for (int i = 0; i < 4; i++) {
            float2 v = *(float2*)&acc[jp * 4 + i];
            s[2 * jp][i]     = -v.x;
            s[2 * jp + 1][i] = -v.y;
        }
    #pragma unroll
    for (int jj = 0; jj < 8; jj++)
        *(float4*)&g_s[((size_t)p * LN + j0 + ty * 8 + jj) * LN + k0 + 4 * tx] =
            make_float4(s[jj][0], s[jj][1], s[jj][2], s[jj][3]);

    // ---- row partials (over this block's 64 cols) ----
    #pragma unroll
    for (int jj = 0; jj < 8; jj++) {
        float m = fmaxf(fmaxf(s[jj][0], s[jj][1]), fmaxf(s[jj][2], s[jj][3]));
        #pragma unroll
        for (int o = 1; o <= 8; o <<= 1) m = fmaxf(m, __shfl_xor_sync(~0u, m, o));
        float e = __expf(s[jj][0] - m) + __expf(s[jj][1] - m) +
                  __expf(s[jj][2] - m) + __expf(s[jj][3] - m);
        #pragma unroll
        for (int o = 1; o <= 8; o <<= 1) e += __shfl_xor_sync(~0u, e, o);
        if (tx == 0) {
            int jg = j0 + ty * 8 + jj;
            g_rpm[((size_t)p * LN + jg) * 8 + kb] = m;
            g_rps[((size_t)p * LN + jg) * 8 + kb] = e;
        }
    }

    // ---- col partials (over this block's 64 rows) ----
    float cm4[4];
    #pragma unroll
    for (int i = 0; i < 4; i++) {
        float m = s[0][i];
        #pragma unroll
        for (int jj = 1; jj < 8; jj++) m = fmaxf(m, s[jj][i]);
        m = fmaxf(m, __shfl_xor_sync(~0u, m, 16));   // ty pair within warp
        cm4[i] = m;
    }
    if ((t & 16) == 0)
        #pragma unroll
        for (int i = 0; i < 4; i++) scm[w][4 * tx + i] = cm4[i];
    __syncthreads();
    if (t < 64)
        scmf[t] = fmaxf(fmaxf(scm[0][t], scm[1][t]), fmaxf(scm[2][t], scm[3][t]));
    __syncthreads();
    #pragma unroll
    for (int i = 0; i < 4; i++) {
        float M = scmf[4 * tx + i];
        float e = 0.f;
        #pragma unroll
        for (int jj = 0; jj < 8; jj++) e += __expf(s[jj][i] - M);
        e += __shfl_xor_sync(~0u, e, 16);
        cm4[i] = e;
    }
    if ((t & 16) == 0)
        #pragma unroll
        for (int i = 0; i < 4; i++) scs[w][4 * tx + i] = cm4[i];
    __syncthreads();
    if (t < 64) {
        int kg = k0 + t;
        g_cpm[((size_t)p * LN + kg) * 8 + jb] = scmf[t];
        g_cps[((size_t)p * LN + kg) * 8 + jb] =
            scs[0][t] + scs[1][t] + scs[2][t] + scs[3][t];
    }
}

// ============ K2: fused combine + reduce + finalize (grid barriers) ==========
__device__ __forceinline__ void gbar(int k, unsigned n) {
    __syncthreads();
    if (threadIdx.x == 0) {
        __threadfence();
        atomicAdd(&g_bar[k], 1u);
        while (((volatile unsigned*)g_bar)[k] < n) { }
    }
    __syncthreads();
}

__global__ __launch_bounds__(256) void k_rest(const float* __restrict__ wgt,
                                              const float* __restrict__ bias,
                                              float* __restrict__ out) {
    const int t = threadIdx.x, b = blockIdx.x;
    const int gt = b * 256 + t;

    // ---- phase A: combine partials -> A_j, B_k (blocks 0..15) ----
    if (gt < 2 * PN * LN) {
        int isCol = gt >= PN * LN;
        int id = isCol ? gt - PN * LN : gt;
        const float* pm = isCol ? g_cpm : g_rpm;
        const float* ps = isCol ? g_cps : g_rps;
        float M = pm[id * 8];
        #pragma unroll
        for (int i = 1; i < 8; i++) M = fmaxf(M, pm[id * 8 + i]);
        float S = 0.f;
        #pragma unroll
        for (int i = 0; i < 8; i++) S += ps[id * 8 + i] * __expf(pm[id * 8 + i] - M);
        float v = __expf(-M) / S;
        if (isCol) g_B[id] = v; else g_A[id] = v;
    }
    gbar(0, 64);

    // ---- phase B: sum(c*s), sum(c) over 32-row band ----
    const int p = b >> 4, chunk = b & 15;
    const float4* S4 = (const float4*)(g_s + (size_t)p * LN * LN + (size_t)chunk * 32 * LN);
    const float*  A  = g_A + p * LN + chunk * 32;
    const float4* B4 = (const float4*)(g_B + p * LN);
    float num = 0.f, den = 0.f;
    #pragma unroll
    for (int i = 0; i < 16; i++) {
        int f  = i * 256 + t;          // 0..4095 float4s (32 rows x 128)
        int jr = f >> 7, kq = f & 127;
        float4 sv = S4[f];
        float4 Bv = B4[kq];
        float Aj = A[jr];
        float E, a, bb, c;
        E = __expf(sv.x); a = E * Aj; bb = E * Bv.x;
        c = a + bb - a * bb; num = fmaf(c, sv.x, num); den += c;
        E = __expf(sv.y); a = E * Aj; bb = E * Bv.y;
        c = a + bb - a * bb; num = fmaf(c, sv.y, num); den += c;
        E = __expf(sv.z); a = E * Aj; bb = E * Bv.z;
        c = a + bb - a * bb; num = fmaf(c, sv.z, num); den += c;
        E = __expf(sv.w); a = E * Aj; bb = E * Bv.w;
        c = a + bb - a * bb; num = fmaf(c, sv.w, num); den += c;
    }
    #pragma unroll
    for (int o = 16; o; o >>= 1) {
        num += __shfl_xor_sync(~0u, num, o);
        den += __shfl_xor_sync(~0u, den, o);
    }
    __shared__ float sn[8], sd[8];
    if ((t & 31) == 0) { sn[t >> 5] = num; sd[t >> 5] = den; }
    __syncthreads();
    if (t == 0) {
        float N = 0.f, D = 0.f;
        #pragma unroll
        for (int q = 0; q < 8; q++) { N += sn[q]; D += sd[q]; }
        g_pn[b] = N; g_pd[b] = D;
    }
    gbar(1, 64);

    // ---- phase C: 16 outputs ----
    if (b == 0 && t < 16) {
        int pp = t >> 2, c = t & 3;
        float N = 0.f, D = 0.f;
        #pragma unroll
        for (int i = 0; i < 16; i++) { N += g_pn[pp * 16 + i]; D += g_pd[pp * 16 + i]; }
        out[t] = (N / D) * wgt[c] + bias[c];
    }
}

// ---------------- launch ----------------
extern "C" void kernel_launch(void* const* d_in, const int* in_sizes, int n_in,
                              void* d_out, int out_size) {
    const float* z = (const float*)d_in[0];   // (8, 512, 64) fp32
    const float* w = (const float*)d_in[1];   // (1, 4)
    const float* b = (const float*)d_in[2];   // (4,)
    float* out = (float*)d_out;               // (4, 4)

    const int smem = (68 + 130) * 64 * 4;     // 50688 B
    cudaFuncSetAttribute(k_s, cudaFuncAttributeMaxDynamicSharedMemorySize, smem);
    k_s   <<<dim3(8, 8, 4), 128, smem>>>(z);
    k_rest<<<64, 256>>>(w, b, out);
}

// round 4
// speedup vs baseline: 1.5188x; 1.0420x over previous
#include <cuda_runtime.h>

#define PN 4
#define LN 512
#define DN 64
typedef unsigned long long ull;

// ---------------- device scratch ----------------
__device__ __align__(16) float g_s[PN * LN * LN];   // 4 MB score matrix
__device__ __align__(16) float g_rps[PN * LN * 8];  // row partial sum e^s (8 kb)
__device__ __align__(16) float g_cps[PN * LN * 8];  // col partial sum e^s (8 jb)
__device__ __align__(16) float g_A[PN * LN];        // 1 / row sumexp
__device__ __align__(16) float g_B[PN * LN];        // 1 / col sumexp
__device__ float g_pn[128], g_pd[128];
__device__ unsigned g_bar[2];

__device__ __forceinline__ ull add2(ull a, ull b) {
    ull r; asm("add.rn.f32x2 %0, %1, %2;" : "=l"(r) : "l"(a), "l"(b)); return r;
}

// ============ K1: 64x64 tiles of s = -sum_d |z0-z1| + partial exp-sums =======
__global__ __launch_bounds__(128) void k_s(const float* __restrict__ z) {
    extern __shared__ float smd[];
    float* z0s = smd;                 // [64][68]  j-major pairs
    float* z1d = smd + 64 * 68;       // [64][130] negated dup pairs, scattered
    __shared__ float scs[4][64];

    const int kb = blockIdx.x, jb = blockIdx.y, p = blockIdx.z;
    const int t = threadIdx.x;
    if (kb == 0 && jb == 0 && p == 0 && t == 0) { g_bar[0] = 0; g_bar[1] = 0; }
    const int j0 = jb * 64, k0 = kb * 64;
    const int tx = t & 15, ty = t >> 4, w = t >> 5;

    const float4* z0g = (const float4*)(z + ((size_t)p * LN + j0) * DN);
    const float4* z1g = (const float4*)(z + ((size_t)(p + PN) * LN + k0) * DN);

    #pragma unroll
    for (int i = 0; i < 8; i++) {
        int f = i * 128 + t;
        int r = f >> 4, dq = f & 15;
        float4 v = z0g[f];
        z0s[(4 * dq + 0) * 68 + r] = v.x;
        z0s[(4 * dq + 1) * 68 + r] = v.y;
        z0s[(4 * dq + 2) * 68 + r] = v.z;
        z0s[(4 * dq + 3) * 68 + r] = v.w;
        float4 u = z1g[f];
        int pr = 2 * ((r & 3) * 16 + (r >> 2));
        *(float2*)(z1d + (4 * dq + 0) * 130 + pr) = make_float2(-u.x, -u.x);
        *(float2*)(z1d + (4 * dq + 1) * 130 + pr) = make_float2(-u.y, -u.y);
        *(float2*)(z1d + (4 * dq + 2) * 130 + pr) = make_float2(-u.z, -u.z);
        *(float2*)(z1d + (4 * dq + 3) * 130 + pr) = make_float2(-u.w, -u.w);
    }
    __syncthreads();

    // thread tile: j = j0 + ty*8..+7 (f32x2 pairs), k = k0 + 4*tx..+3
    ull acc[16];
    #pragma unroll
    for (int q = 0; q < 16; q++) acc[q] = 0;

    #pragma unroll 8
    for (int d = 0; d < DN; d++) {
        ulonglong2 A01 = *(const ulonglong2*)(z0s + d * 68 + ty * 8);
        ulonglong2 A23 = *(const ulonglong2*)(z0s + d * 68 + ty * 8 + 4);
        ull av[4] = { A01.x, A01.y, A23.x, A23.y };
        #pragma unroll
        for (int i = 0; i < 4; i++) {
            ull bv = *(const ull*)(z1d + d * 130 + 32 * i + 2 * tx);
            #pragma unroll
            for (int jp = 0; jp < 4; jp++) {
                ull df = add2(av[jp], bv);
                df &= 0x7fffffff7fffffffULL;
                acc[jp * 4 + i] = add2(acc[jp * 4 + i], df);
            }
        }
    }

    float s[8][4], E[8][4];
    #pragma unroll
    for (int jp = 0; jp < 4; jp++)
        #pragma unroll
        for (int i = 0; i < 4; i++) {
            float2 v = *(float2*)&acc[jp * 4 + i];
            s[2 * jp][i]     = -v.x;
            s[2 * jp + 1][i] = -v.y;
        }
    #pragma unroll
    for (int jj = 0; jj < 8; jj++) {
        *(float4*)&g_s[((size_t)p * LN + j0 + ty * 8 + jj) * LN + k0 + 4 * tx] =
            make_float4(s[jj][0], s[jj][1], s[jj][2], s[jj][3]);
        #pragma unroll
        for (int i = 0; i < 4; i++) E[jj][i] = __expf(s[jj][i]);
    }

    // ---- row partial sums over this block's 64 cols ----
    #pragma unroll
    for (int jj = 0; jj < 8; jj++) {
        float e = (E[jj][0] + E[jj][1]) + (E[jj][2] + E[jj][3]);
        #pragma unroll
        for (int o = 1; o <= 8; o <<= 1) e += __shfl_xor_sync(~0u, e, o);
        if (tx == 0)
            g_rps[((size_t)p * LN + j0 + ty * 8 + jj) * 8 + kb] = e;
    }

    // ---- col partial sums over this block's 64 rows ----
    #pragma unroll
    for (int i = 0; i < 4; i++) {
        float e = ((E[0][i] + E[1][i]) + (E[2][i] + E[3][i])) +
                  ((E[4][i] + E[5][i]) + (E[6][i] + E[7][i]));
        e += __shfl_xor_sync(~0u, e, 16);
        if ((t & 16) == 0) scs[w][4 * tx + i] = e;
    }
    __syncthreads();
    if (t < 64)
        g_cps[((size_t)p * LN + k0 + t) * 8 + jb] =
            (scs[0][t] + scs[1][t]) + (scs[2][t] + scs[3][t]);
}

// ============ K2: fused normalize + reduce + finalize (128 blocks) ===========
__device__ __forceinline__ void gbar(int k, unsigned n) {
    __syncthreads();
    if (threadIdx.x == 0) {
        __threadfence();
        atomicAdd(&g_bar[k], 1u);
        while (((volatile unsigned*)g_bar)[k] < n) { }
        __threadfence();
    }
    __syncthreads();
}

__global__ __launch_bounds__(256) void k_rest(const float* __restrict__ wgt,
                                              const float* __restrict__ bias,
                                              float* __restrict__ out) {
    const int t = threadIdx.x, b = blockIdx.x;
    const int gt = b * 256 + t;

    // ---- phase A: 1/sum over 8 partials (blocks 0..15 active) ----
    if (gt < 2 * PN * LN) {
        int isCol = gt >= PN * LN;
        int id = isCol ? gt - PN * LN : gt;
        const float4* ps = (const float4*)((isCol ? g_cps : g_rps) + id * 8);
        float4 u = ps[0], v = ps[1];
        float S = ((u.x + u.y) + (u.z + u.w)) + ((v.x + v.y) + (v.z + v.w));
        float r = 1.0f / S;
        if (isCol) g_B[id] = r; else g_A[id] = r;
    }
    gbar(0, 128);

    // ---- phase B: sum(c*s), sum(c) over a 16-row band ----
    const int p = b >> 5, chunk = b & 31;
    const float4* S4 = (const float4*)(g_s + (size_t)p * LN * LN) + chunk * 2048;
    const float4* B4 = (const float4*)(g_B + p * LN);

    float4 sv[8];
    #pragma unroll
    for (int i = 0; i < 8; i++) sv[i] = S4[i * 256 + t];   // batched: MLP=8
    float4 Bv = B4[t & 127];

    float num = 0.f, den = 0.f;
    #pragma unroll
    for (int i = 0; i < 8; i++) {
        float Aj = g_A[p * LN + chunk * 16 + i * 2 + (t >> 7)];
        float E, a, bb, c;
        E = __expf(sv[i].x); a = E * Aj; bb = E * Bv.x;
        c = a + bb - a * bb; num = fmaf(c, sv[i].x, num); den += c;
        E = __expf(sv[i].y); a = E * Aj; bb = E * Bv.y;
        c = a + bb - a * bb; num = fmaf(c, sv[i].y, num); den += c;
        E = __expf(sv[i].z); a = E * Aj; bb = E * Bv.z;
        c = a + bb - a * bb; num = fmaf(c, sv[i].z, num); den += c;
        E = __expf(sv[i].w); a = E * Aj; bb = E * Bv.w;
        c = a + bb - a * bb; num = fmaf(c, sv[i].w, num); den += c;
    }
    #pragma unroll
    for (int o = 16; o; o >>= 1) {
        num += __shfl_xor_sync(~0u, num, o);
        den += __shfl_xor_sync(~0u, den, o);
    }
    __shared__ float sn[8], sd[8];
    if ((t & 31) == 0) { sn[t >> 5] = num; sd[t >> 5] = den; }
    __syncthreads();
    if (t == 0) {
        float N = 0.f, D = 0.f;
        #pragma unroll
        for (int q = 0; q < 8; q++) { N += sn[q]; D += sd[q]; }
        g_pn[b] = N; g_pd[b] = D;
    }
    gbar(1, 128);

    // ---- phase C: 16 outputs (block 0, warp w handles pair p=w) ----
    if (b == 0 && t < 128) {
        const int w = t >> 5, l = t & 31;
        float N = g_pn[w * 32 + l], D = g_pd[w * 32 + l];
        #pragma unroll
        for (int o = 16; o; o >>= 1) {
            N += __shfl_xor_sync(~0u, N, o);
            D += __shfl_xor_sync(~0u, D, o);
        }
        if (l == 0) {
            float cv = N / D;
            #pragma unroll
            for (int c = 0; c < 4; c++)
                out[w * 4 + c] = cv * wgt[c] + bias[c];
        }
    }
}

// ---------------- launch ----------------
extern "C" void kernel_launch(void* const* d_in, const int* in_sizes, int n_in,
                              void* d_out, int out_size) {
    const float* z = (const float*)d_in[0];   // (8, 512, 64) fp32
    const float* w = (const float*)d_in[1];   // (1, 4)
    const float* b = (const float*)d_in[2];   // (4,)
    float* out = (float*)d_out;               // (4, 4)

    const int smem = (68 + 130) * 64 * 4;     // 50688 B
    cudaFuncSetAttribute(k_s, cudaFuncAttributeMaxDynamicSharedMemorySize, smem);
    k_s   <<<dim3(8, 8, 4), 128, smem>>>(z);
    k_rest<<<128, 256>>>(w, b, out);
}

// round 5
// speedup vs baseline: 1.6000x; 1.0534x over previous
#include <cuda_runtime.h>

#define PN 4
#define LN 512
#define DN 64
typedef unsigned long long ull;

// ---------------- device scratch ----------------
__device__ __align__(16) float g_s[PN * LN * LN];   // 4 MB score matrix
__device__ __align__(16) float g_rps[PN * LN * 8];  // row partial sum e^s
__device__ __align__(16) float g_cps[PN * LN * 8];  // col partial sum e^s
__device__ __align__(16) float g_A[PN * LN];        // 1 / row sumexp
__device__ __align__(16) float g_B[PN * LN];        // 1 / col sumexp
__device__ __align__(16) float g_pn[256];
__device__ __align__(16) float g_pd[256];
__device__ volatile unsigned g_bar0, g_bar1;        // zero-init; reset by winner
__device__ unsigned g_tick;

__device__ __forceinline__ ull add2(ull a, ull b) {
    ull r; asm("add.rn.f32x2 %0, %1, %2;" : "=l"(r) : "l"(a), "l"(b)); return r;
}

// ============ single persistent kernel ============
__global__ __launch_bounds__(128, 2) void k_all(const float* __restrict__ z,
                                                const float* __restrict__ wgt,
                                                const float* __restrict__ bias,
                                                float* __restrict__ out) {
    extern __shared__ float smd[];
    float* z0s = smd;                 // [64][68]  j-major pairs
    float* z1d = smd + 64 * 68;       // [64][130] negated dup pairs, scattered
    __shared__ float scs[4][64];
    __shared__ float s_n1[4], s_d1[4], s_n2[4], s_d2[4], s_cv[4];
    __shared__ int   s_win;

    const int kb = blockIdx.x, jb = blockIdx.y, p = blockIdx.z;
    const int bid = kb + 8 * jb + 64 * p;
    const int t = threadIdx.x;
    const int j0 = jb * 64, k0 = kb * 64;
    const int tx = t & 15, ty = t >> 4, w = t >> 5;

    // ================= phase 1: score tile + partial exp-sums =================
    {
        const float4* z0g = (const float4*)(z + ((size_t)p * LN + j0) * DN);
        const float4* z1g = (const float4*)(z + ((size_t)(p + PN) * LN + k0) * DN);

        #pragma unroll
        for (int i = 0; i < 8; i++) {
            int f = i * 128 + t;
            int r = f >> 4, dq = f & 15;
            float4 v = z0g[f];
            z0s[(4 * dq + 0) * 68 + r] = v.x;
            z0s[(4 * dq + 1) * 68 + r] = v.y;
            z0s[(4 * dq + 2) * 68 + r] = v.z;
            z0s[(4 * dq + 3) * 68 + r] = v.w;
            float4 u = z1g[f];
            int pr = 2 * ((r & 3) * 16 + (r >> 2));
            *(float2*)(z1d + (4 * dq + 0) * 130 + pr) = make_float2(-u.x, -u.x);
            *(float2*)(z1d + (4 * dq + 1) * 130 + pr) = make_float2(-u.y, -u.y);
            *(float2*)(z1d + (4 * dq + 2) * 130 + pr) = make_float2(-u.z, -u.z);
            *(float2*)(z1d + (4 * dq + 3) * 130 + pr) = make_float2(-u.w, -u.w);
        }
        __syncthreads();

        ull acc[16];
        #pragma unroll
        for (int q = 0; q < 16; q++) acc[q] = 0;

        #pragma unroll 8
        for (int d = 0; d < DN; d++) {
            ulonglong2 A01 = *(const ulonglong2*)(z0s + d * 68 + ty * 8);
            ulonglong2 A23 = *(const ulonglong2*)(z0s + d * 68 + ty * 8 + 4);
            ull av[4] = { A01.x, A01.y, A23.x, A23.y };
            #pragma unroll
            for (int i = 0; i < 4; i++) {
                ull bv = *(const ull*)(z1d + d * 130 + 32 * i + 2 * tx);
                #pragma unroll
                for (int jp = 0; jp < 4; jp++) {
                    ull df = add2(av[jp], bv);
                    df &= 0x7fffffff7fffffffULL;
                    acc[jp * 4 + i] = add2(acc[jp * 4 + i], df);
                }
            }
        }

        float s[8][4], E[8][4];
        #pragma unroll
        for (int jp = 0; jp < 4; jp++)
            #pragma unroll
            for (int i = 0; i < 4; i++) {
                float2 v = *(float2*)&acc[jp * 4 + i];
                s[2 * jp][i]     = -v.x;
                s[2 * jp + 1][i] = -v.y;
            }
        #pragma unroll
        for (int jj = 0; jj < 8; jj++) {
            *(float4*)&g_s[((size_t)p * LN + j0 + ty * 8 + jj) * LN + k0 + 4 * tx] =
                make_float4(s[jj][0], s[jj][1], s[jj][2], s[jj][3]);
            #pragma unroll
            for (int i = 0; i < 4; i++) E[jj][i] = __expf(s[jj][i]);
        }

        #pragma unroll
        for (int jj = 0; jj < 8; jj++) {
            float e = (E[jj][0] + E[jj][1]) + (E[jj][2] + E[jj][3]);
            #pragma unroll
            for (int o = 1; o <= 8; o <<= 1) e += __shfl_xor_sync(~0u, e, o);
            if (tx == 0)
                g_rps[((size_t)p * LN + j0 + ty * 8 + jj) * 8 + kb] = e;
        }
        #pragma unroll
        for (int i = 0; i < 4; i++) {
            float e = ((E[0][i] + E[1][i]) + (E[2][i] + E[3][i])) +
                      ((E[4][i] + E[5][i]) + (E[6][i] + E[7][i]));
            e += __shfl_xor_sync(~0u, e, 16);
            if ((t & 16) == 0) scs[w][4 * tx + i] = e;
        }
        __syncthreads();
        if (t < 64)
            g_cps[((size_t)p * LN + k0 + t) * 8 + jb] =
                (scs[0][t] + scs[1][t]) + (scs[2][t] + scs[3][t]);
    }

    // ---- grid barrier 0 ----
    __threadfence();
    __syncthreads();
    if (t == 0) {
        atomicAdd((unsigned*)&g_bar0, 1u);
        while (g_bar0 < 256u) { }
    }
    __syncthreads();

    // ================= phase A: A_j = 1/rowsum, B_k = 1/colsum =================
    {
        int gt = bid * 128 + t;
        if (gt < 2 * PN * LN) {
            int isCol = gt >= PN * LN;
            int id = isCol ? gt - PN * LN : gt;
            const float4* ps = (const float4*)((isCol ? g_cps : g_rps) + id * 8);
            float4 u = ps[0], v = ps[1];
            float S = ((u.x + u.y) + (u.z + u.w)) + ((v.x + v.y) + (v.z + v.w));
            float r = 1.0f / S;
            if (isCol) g_B[id] = r; else g_A[id] = r;
        }
    }

    // ---- grid barrier 1 ----
    __threadfence();
    __syncthreads();
    if (t == 0) {
        atomicAdd((unsigned*)&g_bar1, 1u);
        while (g_bar1 < 256u) { }
    }
    __syncthreads();

    // ================= phase B: sum(c*s), sum(c) over an 8-row band ============
    {
        const int pp = bid >> 6, band = bid & 63;
        const float4* S4 = (const float4*)(g_s + (size_t)pp * LN * LN +
                                           (size_t)band * 8 * LN);
        float4 Bv = *((const float4*)(g_B + pp * LN) + t);
        float num = 0.f, den = 0.f;
        #pragma unroll
        for (int i = 0; i < 8; i++) {
            float4 sv = S4[i * 128 + t];
            float Aj = g_A[pp * LN + band * 8 + i];
            float E, a, bb, c;
            E = __expf(sv.x); a = E * Aj; bb = E * Bv.x;
            c = a + bb - a * bb; num = fmaf(c, sv.x, num); den += c;
            E = __expf(sv.y); a = E * Aj; bb = E * Bv.y;
            c = a + bb - a * bb; num = fmaf(c, sv.y, num); den += c;
            E = __expf(sv.z); a = E * Aj; bb = E * Bv.z;
            c = a + bb - a * bb; num = fmaf(c, sv.z, num); den += c;
            E = __expf(sv.w); a = E * Aj; bb = E * Bv.w;
            c = a + bb - a * bb; num = fmaf(c, sv.w, num); den += c;
        }
        #pragma unroll
        for (int o = 16; o; o >>= 1) {
            num += __shfl_xor_sync(~0u, num, o);
            den += __shfl_xor_sync(~0u, den, o);
        }
        __shared__ float sn[4], sd[4];
        if ((t & 31) == 0) { sn[w] = num; sd[w] = den; }
        __syncthreads();
        if (t == 0) {
            g_pn[bid] = (sn[0] + sn[1]) + (sn[2] + sn[3]);
            g_pd[bid] = (sd[0] + sd[1]) + (sd[2] + sd[3]);
        }
    }

    // ---- ticket: last block finalizes ----
    __threadfence();
    __syncthreads();
    if (t == 0) s_win = (atomicAdd(&g_tick, 1u) == 255u) ? 1 : 0;
    __syncthreads();
    if (!s_win) return;

    {
        // 256 partials: thread t handles partial t (p = t>>6) and t+128 (p+2)
        float n1 = __ldcg(&g_pn[t]),       d1 = __ldcg(&g_pd[t]);
        float n2 = __ldcg(&g_pn[t + 128]), d2 = __ldcg(&g_pd[t + 128]);
        #pragma unroll
        for (int o = 16; o; o >>= 1) {
            n1 += __shfl_xor_sync(~0u, n1, o);
            d1 += __shfl_xor_sync(~0u, d1, o);
            n2 += __shfl_xor_sync(~0u, n2, o);
            d2 += __shfl_xor_sync(~0u, d2, o);
        }
        if ((t & 31) == 0) { s_n1[w] = n1; s_d1[w] = d1; s_n2[w] = n2; s_d2[w] = d2; }
        __syncthreads();
        if (t < 4) {                        // t = p index
            int lo = 2 * (t & 1);
            float N = (t < 2) ? s_n1[lo] + s_n1[lo + 1] : s_n2[lo] + s_n2[lo + 1];
            float D = (t < 2) ? s_d1[lo] + s_d1[lo + 1] : s_d2[lo] + s_d2[lo + 1];
            s_cv[t] = N / D;
        }
        __syncthreads();
        if (t < 16) out[t] = s_cv[t >> 2] * wgt[t & 3] + bias[t & 3];
        if (t == 0) {                       // reset for next graph replay
            g_bar0 = 0; g_bar1 = 0; g_tick = 0;
        }
    }
}

// ---------------- launch ----------------
extern "C" void kernel_launch(void* const* d_in, const int* in_sizes, int n_in,
                              void* d_out, int out_size) {
    const float* z = (const float*)d_in[0];   // (8, 512, 64) fp32
    const float* w = (const float*)d_in[1];   // (1, 4)
    const float* b = (const float*)d_in[2];   // (4,)
    float* out = (float*)d_out;               // (4, 4)

    const int smem = (68 + 130) * 64 * 4;     // 50688 B dynamic
    cudaFuncSetAttribute(k_all, cudaFuncAttributeMaxDynamicSharedMemorySize, smem);
    k_all<<<dim3(8, 8, 4), 128, smem>>>(z, w, b, out);
}

// round 6
// speedup vs baseline: 1.6123x; 1.0077x over previous
#include <cuda_runtime.h>

#define PN 4
#define LN 512
#define DN 64
typedef unsigned long long ull;

// ---------------- device scratch ----------------
__device__ __align__(16) float g_rps[PN * LN * 8];  // row partial sum e^s (8 kb)
__device__ __align__(16) float g_cps[PN * LN * 8];  // col partial sum e^s (8 jb)
__device__ __align__(16) float g_A[PN * LN];        // 1 / row sumexp
__device__ __align__(16) float g_B[PN * LN];        // 1 / col sumexp
__device__ __align__(16) float g_pn[256];
__device__ __align__(16) float g_pd[256];
__device__ volatile unsigned g_bar0, g_bar1;        // zero-init; winner resets
__device__ unsigned g_tick;

__device__ __forceinline__ ull add2(ull a, ull b) {
    ull r; asm("add.rn.f32x2 %0, %1, %2;" : "=l"(r) : "l"(a), "l"(b)); return r;
}

// ============ single persistent kernel, 256 thr/block, tile 64x64 ============
__global__ __launch_bounds__(256, 2) void k_all(const float* __restrict__ z,
                                                const float* __restrict__ wgt,
                                                const float* __restrict__ bias,
                                                float* __restrict__ out) {
    extern __shared__ float smd[];
    float* z0s = smd;                 // [64][68]  j-major pairs
    float* z1d = smd + 64 * 68;       // [64][130] negated dup pairs, scattered
    __shared__ float scs[8][64];
    __shared__ float sn[8], sd[8];
    __shared__ float s_cv[4];
    __shared__ int   s_win;

    const int kb = blockIdx.x, jb = blockIdx.y, p = blockIdx.z;
    const int bid = kb + 8 * jb + 64 * p;
    const int t = threadIdx.x;
    const int j0 = jb * 64, k0 = kb * 64;
    const int tx = t & 15, ty = t >> 4, w = t >> 5;

    // ================= phase 1: score tile, s & E stay in registers ==========
    const float4* z0g = (const float4*)(z + ((size_t)p * LN + j0) * DN);
    const float4* z1g = (const float4*)(z + ((size_t)(p + PN) * LN + k0) * DN);

    #pragma unroll
    for (int i = 0; i < 4; i++) {
        int f = i * 256 + t;           // 0..1023 float4s
        int r = f >> 4, dq = f & 15;   // row, d-quad
        float4 v = z0g[f];
        z0s[(4 * dq + 0) * 68 + r] = v.x;
        z0s[(4 * dq + 1) * 68 + r] = v.y;
        z0s[(4 * dq + 2) * 68 + r] = v.z;
        z0s[(4 * dq + 3) * 68 + r] = v.w;
        float4 u = z1g[f];
        int pr = 2 * ((r & 3) * 16 + (r >> 2));
        *(float2*)(z1d + (4 * dq + 0) * 130 + pr) = make_float2(-u.x, -u.x);
        *(float2*)(z1d + (4 * dq + 1) * 130 + pr) = make_float2(-u.y, -u.y);
        *(float2*)(z1d + (4 * dq + 2) * 130 + pr) = make_float2(-u.z, -u.z);
        *(float2*)(z1d + (4 * dq + 3) * 130 + pr) = make_float2(-u.w, -u.w);
    }
    __syncthreads();

    // thread tile: j = j0 + ty*4 .. +3 (2 f32x2 pairs), k = k0 + 4*tx .. +3
    ull acc[8];                        // [jp][i]
    #pragma unroll
    for (int q = 0; q < 8; q++) acc[q] = 0;

    #pragma unroll 8
    for (int d = 0; d < DN; d++) {
        ulonglong2 A01 = *(const ulonglong2*)(z0s + d * 68 + ty * 4);
        ull av[2] = { A01.x, A01.y };
        #pragma unroll
        for (int i = 0; i < 4; i++) {
            ull bv = *(const ull*)(z1d + d * 130 + 32 * i + 2 * tx);  // (-bk,-bk)
            #pragma unroll
            for (int jp = 0; jp < 2; jp++) {
                ull df = add2(av[jp], bv);
                df &= 0x7fffffff7fffffffULL;
                acc[jp * 4 + i] = add2(acc[jp * 4 + i], df);
            }
        }
    }

    float s[4][4], E[4][4];
    #pragma unroll
    for (int jp = 0; jp < 2; jp++)
        #pragma unroll
        for (int i = 0; i < 4; i++) {
            float2 v = *(float2*)&acc[jp * 4 + i];
            s[2 * jp][i]     = -v.x;
            s[2 * jp + 1][i] = -v.y;
        }
    #pragma unroll
    for (int jj = 0; jj < 4; jj++)
        #pragma unroll
        for (int i = 0; i < 4; i++) E[jj][i] = __expf(s[jj][i]);

    // ---- row partial sums over this block's 64 cols (shfl across 16 tx) ----
    #pragma unroll
    for (int jj = 0; jj < 4; jj++) {
        float e = (E[jj][0] + E[jj][1]) + (E[jj][2] + E[jj][3]);
        #pragma unroll
        for (int o = 1; o <= 8; o <<= 1) e += __shfl_xor_sync(~0u, e, o);
        if (tx == 0)
            g_rps[((size_t)p * LN + j0 + ty * 4 + jj) * 8 + kb] = e;
    }

    // ---- col partial sums over this block's 64 rows ----
    #pragma unroll
    for (int i = 0; i < 4; i++) {
        float e = (E[0][i] + E[1][i]) + (E[2][i] + E[3][i]);
        e += __shfl_xor_sync(~0u, e, 16);         // combine the 2 ty in warp
        if ((t & 16) == 0) scs[w][4 * tx + i] = e;
    }
    __syncthreads();
    if (t < 64) {
        float e = ((scs[0][t] + scs[1][t]) + (scs[2][t] + scs[3][t])) +
                  ((scs[4][t] + scs[5][t]) + (scs[6][t] + scs[7][t]));
        g_cps[((size_t)p * LN + k0 + t) * 8 + jb] = e;
    }

    // ---- grid barrier 0 ----
    __threadfence();
    __syncthreads();
    if (t == 0) {
        atomicAdd((unsigned*)&g_bar0, 1u);
        while (g_bar0 < 256u) { }
    }
    __syncthreads();

    // ================= phase A: A_j = 1/rowsum, B_k = 1/colsum ===============
    if (bid < 16) {
        int gt = bid * 256 + t;        // 0..4095
        int isCol = gt >= PN * LN;
        int id = isCol ? gt - PN * LN : gt;
        const float4* ps = (const float4*)((isCol ? g_cps : g_rps) + id * 8);
        float4 u = __ldcg(ps), v = __ldcg(ps + 1);
        float S = ((u.x + u.y) + (u.z + u.w)) + ((v.x + v.y) + (v.z + v.w));
        float r = 1.0f / S;
        if (isCol) g_B[id] = r; else g_A[id] = r;
    }

    // ---- grid barrier 1 ----
    __threadfence();
    __syncthreads();
    if (t == 0) {
        atomicAdd((unsigned*)&g_bar1, 1u);
        while (g_bar1 < 256u) { }
    }
    __syncthreads();

    // ================= phase C: own-tile sum(c*s), sum(c) from registers =====
    {
        float4 Av = __ldcg((const float4*)(g_A + p * LN + j0 + ty * 4));
        float4 Bv = __ldcg((const float4*)(g_B + p * LN + k0 + 4 * tx));
        const float Aj[4] = { Av.x, Av.y, Av.z, Av.w };
        const float Bk[4] = { Bv.x, Bv.y, Bv.z, Bv.w };
        float num = 0.f, den = 0.f;
        #pragma unroll
        for (int jj = 0; jj < 4; jj++)
            #pragma unroll
            for (int i = 0; i < 4; i++) {
                float a = E[jj][i] * Aj[jj];
                float b = E[jj][i] * Bk[i];
                float c = a + b - a * b;
                num = fmaf(c, s[jj][i], num);
                den += c;
            }
        #pragma unroll
        for (int o = 16; o; o >>= 1) {
            num += __shfl_xor_sync(~0u, num, o);
            den += __shfl_xor_sync(~0u, den, o);
        }
        if ((t & 31) == 0) { sn[w] = num; sd[w] = den; }
        __syncthreads();
        if (t == 0) {
            g_pn[bid] = ((sn[0] + sn[1]) + (sn[2] + sn[3])) +
                        ((sn[4] + sn[5]) + (sn[6] + sn[7]));
            g_pd[bid] = ((sd[0] + sd[1]) + (sd[2] + sd[3])) +
                        ((sd[4] + sd[5]) + (sd[6] + sd[7]));
        }
    }

    // ---- ticket: last block finalizes ----
    __threadfence();
    __syncthreads();
    if (t == 0) s_win = (atomicAdd(&g_tick, 1u) == 255u) ? 1 : 0;
    __syncthreads();
    if (!s_win) return;

    {
        // 256 partials, 256 threads; partial t belongs to pair p = t>>6
        float N = __ldcg(&g_pn[t]), D = __ldcg(&g_pd[t]);
        #pragma unroll
        for (int o = 16; o; o >>= 1) {
            N += __shfl_xor_sync(~0u, N, o);
            D += __shfl_xor_sync(~0u, D, o);
        }
        if ((t & 31) == 0) { sn[w] = N; sd[w] = D; }   // sn[w]: warps 2q,2q+1 -> p=q
        __syncthreads();
        if (t < 4) s_cv[t] = (sn[2 * t] + sn[2 * t + 1]) / (sd[2 * t] + sd[2 * t + 1]);
        __syncthreads();
        if (t < 16) out[t] = s_cv[t >> 2] * wgt[t & 3] + bias[t & 3];
        if (t == 0) { g_bar0 = 0; g_bar1 = 0; g_tick = 0; }   // reset for replay
    }
}

// ---------------- launch ----------------
extern "C" void kernel_launch(void* const* d_in, const int* in_sizes, int n_in,
                              void* d_out, int out_size) {
    const float* z = (const float*)d_in[0];   // (8, 512, 64) fp32
    const float* w = (const float*)d_in[1];   // (1, 4)
    const float* b = (const float*)d_in[2];   // (4,)
    float* out = (float*)d_out;               // (4, 4)

    const int smem = (68 + 130) * 64 * 4;     // 50688 B dynamic
    cudaFuncSetAttribute(k_all, cudaFuncAttributeMaxDynamicSharedMemorySize, smem);
    k_all<<<dim3(8, 8, 4), 256, smem>>>(z, w, b, out);
}

// round 7
// speedup vs baseline: 1.6349x; 1.0140x over previous
#include <cuda_runtime.h>

#define PN 4
#define LN 512
#define DN 64
typedef unsigned long long ull;

// ---------------- device scratch ----------------
__device__ __align__(16) float g_rps[PN * LN * 8];  // row partial sum e^s (8 kb)
__device__ __align__(16) float g_cps[PN * LN * 8];  // col partial sum e^s (8 jb)
__device__ __align__(16) float g_pn[256];
__device__ __align__(16) float g_pd[256];
__device__ volatile unsigned g_bar0;                // zero-init; winner resets
__device__ unsigned g_tick;

__device__ __forceinline__ ull add2(ull a, ull b) {
    ull r; asm("add.rn.f32x2 %0, %1, %2;" : "=l"(r) : "l"(a), "l"(b)); return r;
}

// ============ single persistent kernel, 256 thr, 64x64 tiles ============
// smem: z0s [64 d][64 j]   pitch 64, 16B-block col swizzle:  blk' = blk ^ (d>>2)
//       z1d [64 d][128]    dup pairs (-b,-b), pitch 128, same swizzle
// All prologue STS and mainloop LDS are bank-conflict-free under this swizzle.
__global__ __launch_bounds__(256, 2) void k_all(const float* __restrict__ z,
                                                const float* __restrict__ wgt,
                                                const float* __restrict__ bias,
                                                float* __restrict__ out) {
    extern __shared__ float smd[];
    float* z0s = smd;                 // 16 KB
    float* z1d = smd + 64 * 64;       // 32 KB
    __shared__ float scs[8][64];
    __shared__ float sA[64], sB[64];
    __shared__ float sn[8], sd[8];
    __shared__ float s_cv[4];
    __shared__ int   s_win;

    const int kb = blockIdx.x, jb = blockIdx.y, p = blockIdx.z;
    const int bid = kb + 8 * jb + 64 * p;
    const int t = threadIdx.x;
    const int j0 = jb * 64, k0 = kb * 64;
    const int tx = t & 15, ty = t >> 4, w = t >> 5;

    // ================= prologue: gmem -> swizzled smem =================
    const float4* z0g = (const float4*)(z + ((size_t)p * LN + j0) * DN);
    const float4* z1g = (const float4*)(z + ((size_t)(p + PN) * LN + k0) * DN);

    #pragma unroll
    for (int i = 0; i < 4; i++) {
        int f = i * 256 + t;           // 0..1023 float4s
        int r = f >> 4, dq = f & 15;   // row, d-quad (d = 4*dq+c)
        float4 v = z0g[f];
        int c0 = ((((r >> 2) ^ dq) << 2) | (r & 3));
        z0s[(4 * dq + 0) * 64 + c0] = v.x;
        z0s[(4 * dq + 1) * 64 + c0] = v.y;
        z0s[(4 * dq + 2) * 64 + c0] = v.z;
        z0s[(4 * dq + 3) * 64 + c0] = v.w;
        float4 u = z1g[f];
        int c1 = ((((r >> 1) ^ dq) << 2) | ((r & 1) << 1));
        *(float2*)(z1d + (4 * dq + 0) * 128 + c1) = make_float2(-u.x, -u.x);
        *(float2*)(z1d + (4 * dq + 1) * 128 + c1) = make_float2(-u.y, -u.y);
        *(float2*)(z1d + (4 * dq + 2) * 128 + c1) = make_float2(-u.z, -u.z);
        *(float2*)(z1d + (4 * dq + 3) * 128 + c1) = make_float2(-u.w, -u.w);
    }
    __syncthreads();

    // ================= mainloop: j = 4ty..+3, k = 4tx..+3 =================
    ull acc[8];                        // [jp][i]: jp = j-pair, i = k
    #pragma unroll
    for (int q = 0; q < 8; q++) acc[q] = 0;

    #pragma unroll 16
    for (int d = 0; d < DN; d++) {
        int q = d >> 2;
        ulonglong2 av = *(const ulonglong2*)(z0s + d * 64 + ((ty ^ q) << 2));
        ulonglong2 bA = *(const ulonglong2*)(z1d + d * 128 + (((2 * tx) ^ q) << 2));
        ulonglong2 bB = *(const ulonglong2*)(z1d + d * 128 + (((2 * tx + 1) ^ q) << 2));
        ull ap[2] = { av.x, av.y };               // (a0,a1) (a2,a3)
        ull bp[4] = { bA.x, bA.y, bB.x, bB.y };   // (-bk,-bk) for k=0..3
        #pragma unroll
        for (int i = 0; i < 4; i++)
            #pragma unroll
            for (int jp = 0; jp < 2; jp++) {
                ull df = add2(ap[jp], bp[i]);
                df &= 0x7fffffff7fffffffULL;
                acc[jp * 4 + i] = add2(acc[jp * 4 + i], df);
            }
    }

    float s[4][4], E[4][4];
    #pragma unroll
    for (int jp = 0; jp < 2; jp++)
        #pragma unroll
        for (int i = 0; i < 4; i++) {
            float2 v = *(float2*)&acc[jp * 4 + i];
            s[2 * jp][i]     = -v.x;
            s[2 * jp + 1][i] = -v.y;
        }
    #pragma unroll
    for (int jj = 0; jj < 4; jj++)
        #pragma unroll
        for (int i = 0; i < 4; i++) E[jj][i] = __expf(s[jj][i]);

    // ---- row partial sums (64 cols of this block) ----
    #pragma unroll
    for (int jj = 0; jj < 4; jj++) {
        float e = (E[jj][0] + E[jj][1]) + (E[jj][2] + E[jj][3]);
        #pragma unroll
        for (int o = 1; o <= 8; o <<= 1) e += __shfl_xor_sync(~0u, e, o);
        if (tx == 0)
            g_rps[((size_t)p * LN + j0 + 4 * ty + jj) * 8 + kb] = e;
    }

    // ---- col partial sums (64 rows of this block) ----
    #pragma unroll
    for (int i = 0; i < 4; i++) {
        float e = (E[0][i] + E[1][i]) + (E[2][i] + E[3][i]);
        e += __shfl_xor_sync(~0u, e, 16);
        if ((t & 16) == 0) scs[w][4 * tx + i] = e;
    }
    __syncthreads();
    if (t < 64) {
        float e = ((scs[0][t] + scs[1][t]) + (scs[2][t] + scs[3][t])) +
                  ((scs[4][t] + scs[5][t]) + (scs[6][t] + scs[7][t]));
        g_cps[((size_t)p * LN + k0 + t) * 8 + jb] = e;
    }

    // ---- grid barrier ----
    __threadfence();
    __syncthreads();
    if (t == 0) {
        atomicAdd((unsigned*)&g_bar0, 1u);
        while (g_bar0 < 256u) { }
    }
    __syncthreads();

    // ---- per-block A/B: redundant recompute, no second grid barrier ----
    if (t < 128) {
        int isCol = t >> 6, id = t & 63;
        const float4* ps = (const float4*)((isCol ? g_cps + ((size_t)p * LN + k0 + id) * 8
                                                  : g_rps + ((size_t)p * LN + j0 + id) * 8));
        float4 u = __ldcg(ps), v = __ldcg(ps + 1);
        float S = ((u.x + u.y) + (u.z + u.w)) + ((v.x + v.y) + (v.z + v.w));
        if (isCol) sB[id] = 1.0f / S; else sA[id] = 1.0f / S;
    }
    __syncthreads();

    // ---- phase C: own-tile sum(c*s), sum(c) from registers ----
    {
        float4 Av = *(const float4*)&sA[4 * ty];
        float4 Bv = *(const float4*)&sB[4 * tx];
        const float Aj[4] = { Av.x, Av.y, Av.z, Av.w };
        const float Bk[4] = { Bv.x, Bv.y, Bv.z, Bv.w };
        float num = 0.f, den = 0.f;
        #pragma unroll
        for (int jj = 0; jj < 4; jj++)
            #pragma unroll
            for (int i = 0; i < 4; i++) {
                float a = E[jj][i] * Aj[jj];
                float b = E[jj][i] * Bk[i];
                float c = a + b - a * b;
                num = fmaf(c, s[jj][i], num);
                den += c;
            }
        #pragma unroll
        for (int o = 16; o; o >>= 1) {
            num += __shfl_xor_sync(~0u, num, o);
            den += __shfl_xor_sync(~0u, den, o);
        }
        if ((t & 31) == 0) { sn[w] = num; sd[w] = den; }
        __syncthreads();
        if (t == 0) {
            g_pn[bid] = ((sn[0] + sn[1]) + (sn[2] + sn[3])) +
                        ((sn[4] + sn[5]) + (sn[6] + sn[7]));
            g_pd[bid] = ((sd[0] + sd[1]) + (sd[2] + sd[3])) +
                        ((sd[4] + sd[5]) + (sd[6] + sd[7]));
        }
    }

    // ---- ticket: last block finalizes ----
    __threadfence();
    __syncthreads();
    if (t == 0) s_win = (atomicAdd(&g_tick, 1u) == 255u) ? 1 : 0;
    __syncthreads();
    if (!s_win) return;

    {
        float N = __ldcg(&g_pn[t]), D = __ldcg(&g_pd[t]);
        #pragma unroll
        for (int o = 16; o; o >>= 1) {
            N += __shfl_xor_sync(~0u, N, o);
            D += __shfl_xor_sync(~0u, D, o);
        }
        if ((t & 31) == 0) { sn[w] = N; sd[w] = D; }
        __syncthreads();
        if (t < 4) s_cv[t] = (sn[2 * t] + sn[2 * t + 1]) / (sd[2 * t] + sd[2 * t + 1]);
        __syncthreads();
        if (t < 16) out[t] = s_cv[t >> 2] * wgt[t & 3] + bias[t & 3];
        if (t == 0) { g_bar0 = 0; g_tick = 0; }   // reset for graph replay
    }
}

// ---------------- launch ----------------
extern "C" void kernel_launch(void* const* d_in, const int* in_sizes, int n_in,
                              void* d_out, int out_size) {
    const float* z = (const float*)d_in[0];   // (8, 512, 64) fp32
    const float* w = (const float*)d_in[1];   // (1, 4)
    const float* b = (const float*)d_in[2];   // (4,)
    float* out = (float*)d_out;               // (4, 4)

    const int smem = (64 + 128) * 64 * 4;     // 49152 B dynamic
    cudaFuncSetAttribute(k_all, cudaFuncAttributeMaxDynamicSharedMemorySize, smem);
    k_all<<<dim3(8, 8, 4), 256, smem>>>(z, w, b, out);
}

// round 8
// speedup vs baseline: 1.7733x; 1.0846x over previous
#include <cuda_runtime.h>

#define PN 4
#define LN 512
#define DN 64
typedef unsigned long long ull;

// ---------------- device scratch ----------------
__device__ __align__(16) float g_rps[PN * LN * 4];  // row partial sums (4 kb)
__device__ __align__(16) float g_cps[PN * LN * 8];  // col partial sums (8 jb)
__device__ __align__(16) float g_pn[128];
__device__ __align__(16) float g_pd[128];
__device__ volatile unsigned g_bar0;                // zero-init; winner resets
__device__ unsigned g_tick;

__device__ __forceinline__ ull add2(ull a, ull b) {
    ull r; asm("add.rn.f32x2 %0, %1, %2;" : "=l"(r) : "l"(a), "l"(b)); return r;
}

// ============ single persistent kernel: 128 blocks, 256 thr, 64j x 128k ======
// smem: z0d [64 d][130]  dup pairs (aj,aj), pitch 130 (8B-aligned rows)
//       z1n [64 d][128]  = -z1, natural k order
// Warp = one j-octet: a-loads are warp-broadcast LDS.64 (no crossbar cost);
// b-load is one conflict-free LDS.128 per d. f32x2 packs over k.
__global__ __launch_bounds__(256, 1) void k_all(const float* __restrict__ z,
                                                const float* __restrict__ wgt,
                                                const float* __restrict__ bias,
                                                float* __restrict__ out) {
    extern __shared__ float smd[];
    float* z0d = smd;                 // 64*130 floats
    float* z1n = smd + 64 * 130;      // 64*128 floats
    __shared__ float scs[8][128];
    __shared__ float sA[64], sB[128];
    __shared__ float sn[8], sd[8];
    __shared__ int   s_win;

    const int kb = blockIdx.x, jb = blockIdx.y, p = blockIdx.z;
    const int bid = kb + 4 * jb + 32 * p;       // 0..127
    const int t  = threadIdx.x;
    const int j0 = jb * 64, k0 = kb * 128;
    const int tx = t & 31, ty = t >> 5;         // k-quad lane, j-octet warp

    const float4* z0g = (const float4*)(z + ((size_t)p * LN + j0) * DN);
    const float4* z1g = (const float4*)(z + ((size_t)(p + PN) * LN + k0) * DN);

    // ---- prologue: z0 -> dup pairs (bank-friendly lane remap) ----
    #pragma unroll
    for (int i = 0; i < 4; i++) {
        int r  = (t & 31) | ((i & 1) << 5);     // j row 0..63
        int dq = (t >> 5) | ((i >> 1) << 3);    // d quad 0..15
        float4 v = z0g[r * 16 + dq];
        *(float2*)(z0d + (4 * dq + 0) * 130 + 2 * r) = make_float2(v.x, v.x);
        *(float2*)(z0d + (4 * dq + 1) * 130 + 2 * r) = make_float2(v.y, v.y);
        *(float2*)(z0d + (4 * dq + 2) * 130 + 2 * r) = make_float2(v.z, v.z);
        *(float2*)(z0d + (4 * dq + 3) * 130 + 2 * r) = make_float2(v.w, v.w);
    }
    // ---- prologue: z1 -> negated natural (conflict-free STS.32) ----
    #pragma unroll
    for (int i = 0; i < 8; i++) {
        int r  = (t & 31) | ((i & 3) << 5);     // k row 0..127
        int dq = (t >> 5) | ((i >> 2) << 3);
        float4 u = z1g[r * 16 + dq];
        z1n[(4 * dq + 0) * 128 + r] = -u.x;
        z1n[(4 * dq + 1) * 128 + r] = -u.y;
        z1n[(4 * dq + 2) * 128 + r] = -u.z;
        z1n[(4 * dq + 3) * 128 + r] = -u.w;
    }
    __syncthreads();

    // ---- mainloop: j = 8*ty..+7, k = 4*tx..+3, acc = sum_d |a-b| >= 0 ----
    ull acc[16];                                 // [jj][kp]
    #pragma unroll
    for (int q = 0; q < 16; q++) acc[q] = 0;

    #pragma unroll 4
    for (int d = 0; d < DN; d++) {
        ulonglong2 bv = *(const ulonglong2*)(z1n + d * 128 + 4 * tx);
        ull bp0 = bv.x, bp1 = bv.y;              // (-bk0,-bk1) (-bk2,-bk3)
        #pragma unroll
        for (int jj = 0; jj < 8; jj++) {
            ull ap = *(const ull*)(z0d + d * 130 + 2 * (8 * ty + jj)); // bcast
            ull d0 = add2(ap, bp0) & 0x7fffffff7fffffffULL;
            ull d1 = add2(ap, bp1) & 0x7fffffff7fffffffULL;
            acc[jj * 2 + 0] = add2(acc[jj * 2 + 0], d0);
            acc[jj * 2 + 1] = add2(acc[jj * 2 + 1], d1);
        }
    }

    // ---- epilogue: E = exp(-acc); negations folded into modifiers ----
    float va[8][4], E[8][4];
    #pragma unroll
    for (int jj = 0; jj < 8; jj++) {
        float2 v0 = *(float2*)&acc[jj * 2 + 0];
        float2 v1 = *(float2*)&acc[jj * 2 + 1];
        va[jj][0] = v0.x; va[jj][1] = v0.y; va[jj][2] = v1.x; va[jj][3] = v1.y;
        #pragma unroll
        for (int i = 0; i < 4; i++) E[jj][i] = __expf(-va[jj][i]);
    }

    // ---- row partial sums (this block's 128 k = full warp) ----
    #pragma unroll
    for (int jj = 0; jj < 8; jj++) {
        float e = (E[jj][0] + E[jj][1]) + (E[jj][2] + E[jj][3]);
        #pragma unroll
        for (int o = 16; o; o >>= 1) e += __shfl_xor_sync(~0u, e, o);
        if (tx == 0)
            g_rps[((size_t)p * LN + j0 + 8 * ty + jj) * 4 + kb] = e;
    }

    // ---- col partial sums (this block's 64 j = 8 warps) ----
    {
        float c0 = 0, c1 = 0, c2 = 0, c3 = 0;
        #pragma unroll
        for (int jj = 0; jj < 8; jj++) {
            c0 += E[jj][0]; c1 += E[jj][1]; c2 += E[jj][2]; c3 += E[jj][3];
        }
        *(float4*)&scs[ty][4 * tx] = make_float4(c0, c1, c2, c3);
    }
    __syncthreads();
    if (t < 128) {
        float e = ((scs[0][t] + scs[1][t]) + (scs[2][t] + scs[3][t])) +
                  ((scs[4][t] + scs[5][t]) + (scs[6][t] + scs[7][t]));
        g_cps[((size_t)p * LN + k0 + t) * 8 + jb] = e;
    }

    // ---- grid barrier (128 co-resident blocks) ----
    __threadfence();
    __syncthreads();
    if (t == 0) {
        atomicAdd((unsigned*)&g_bar0, 1u);
        while (g_bar0 < 128u) { }
    }
    __syncthreads();

    // ---- per-block A (64 j) and B (128 k) from partials ----
    if (t < 64) {
        float4 u = __ldcg((const float4*)(g_rps + ((size_t)p * LN + j0 + t) * 4));
        sA[t] = 1.0f / ((u.x + u.y) + (u.z + u.w));
    } else if (t < 192) {
        int id = t - 64;
        const float4* q = (const float4*)(g_cps + ((size_t)p * LN + k0 + id) * 8);
        float4 u = __ldcg(q), v = __ldcg(q + 1);
        sB[id] = 1.0f / (((u.x + u.y) + (u.z + u.w)) + ((v.x + v.y) + (v.z + v.w)));
    }
    __syncthreads();

    // ---- phase C: own-tile sum(c*s), sum(c); s = -va ----
    {
        float4 Bv = *(const float4*)&sB[4 * tx];
        const float Bk[4] = { Bv.x, Bv.y, Bv.z, Bv.w };
        float num = 0.f, den = 0.f;
        #pragma unroll
        for (int jj = 0; jj < 8; jj++) {
            float Aj = sA[8 * ty + jj];          // broadcast
            #pragma unroll
            for (int i = 0; i < 4; i++) {
                float a = E[jj][i] * Aj;
                float b = E[jj][i] * Bk[i];
                float c = a + b - a * b;
                num = fmaf(c, -va[jj][i], num);  // negation via modifier
                den += c;
            }
        }
        #pragma unroll
        for (int o = 16; o; o >>= 1) {
            num += __shfl_xor_sync(~0u, num, o);
            den += __shfl_xor_sync(~0u, den, o);
        }
        if (tx == 0) { sn[ty] = num; sd[ty] = den; }
        __syncthreads();
        if (t == 0) {
            g_pn[bid] = ((sn[0] + sn[1]) + (sn[2] + sn[3])) +
                        ((sn[4] + sn[5]) + (sn[6] + sn[7]));
            g_pd[bid] = ((sd[0] + sd[1]) + (sd[2] + sd[3])) +
                        ((sd[4] + sd[5]) + (sd[6] + sd[7]));
        }
    }

    // ---- ticket: last block finalizes ----
    __threadfence();
    __syncthreads();
    if (t == 0) s_win = (atomicAdd(&g_tick, 1u) == 127u) ? 1 : 0;
    __syncthreads();
    if (!s_win) return;

    if (t < 128) {                               // warp w == pair p
        float N = __ldcg(&g_pn[t]), D = __ldcg(&g_pd[t]);
        #pragma unroll
        for (int o = 16; o; o >>= 1) {
            N += __shfl_xor_sync(~0u, N, o);
            D += __shfl_xor_sync(~0u, D, o);
        }
        if ((t & 31) == 0) {
            float cv = N / D;
            int pp = t >> 5;
            #pragma unroll
            for (int c = 0; c < 4; c++)
                out[pp * 4 + c] = cv * wgt[c] + bias[c];
        }
    }
    if (t == 0) { g_bar0 = 0; g_tick = 0; }      // reset for graph replay
}

// ---------------- launch ----------------
extern "C" void kernel_launch(void* const* d_in, const int* in_sizes, int n_in,
                              void* d_out, int out_size) {
    const float* z = (const float*)d_in[0];   // (8, 512, 64) fp32
    const float* w = (const float*)d_in[1];   // (1, 4)
    const float* b = (const float*)d_in[2];   // (4,)
    float* out = (float*)d_out;               // (4, 4)

    const int smem = (130 + 128) * 64 * 4;    // 66048 B dynamic
    cudaFuncSetAttribute(k_all, cudaFuncAttributeMaxDynamicSharedMemorySize, smem);
    k_all<<<dim3(4, 8, 4), 256, smem>>>(z, w, b, out);
}